// round 15
// baseline (speedup 1.0000x reference)
#include <cuda_runtime.h>
#include <cuda_bf16.h>
#include <math.h>
#include <stdint.h>

// Problem constants
#define NB 32
#define NS 2048
#define ND 1024

// GEMM tiling: CTA 128(M) x 128(N), K chunks of 32
#define MT_TILES 512          // 65536 / 128
#define NT_TILES 8            // 1024 / 128
#define NKC 32                // K chunks of 32 (K = 1024)
#define A_BYTES 16384         // 128 rows x 128 B (32 fp32), 8-chunk XOR swizzle
#define TILE_B 8192           // 128 rows x 64 B (32 bf16), 4-chunk XOR swizzle
#define STAGE_BYTES (A_BYTES + 2 * TILE_B)   // A_f32, Bh, Bl = 32768
#define N_STAGES 3
#define SMEM_STAGES (N_STAGES * STAGE_BYTES) // 98304
#define MB_OFF SMEM_STAGES
#define SMEM_GEMM (SMEM_STAGES + 64)         // 98368 B -> 2 CTAs/SM
#define GT 256                               // 8 warps

// Swizzled byte offset within a B tile (64 B rows, 4 chunks of 16 B)
__device__ __forceinline__ uint32_t swB(uint32_t r, uint32_t c) {
    return r * 64u + ((c ^ ((r >> 1) & 3u)) * 16u);
}
// Swizzled byte offset within the A fp32 tile (128 B rows, 8 chunks of 16 B)
__device__ __forceinline__ uint32_t swA(uint32_t r, uint32_t c) {
    return r * 128u + ((c ^ (r & 7u)) * 16u);
}

// ---------------------------------------------------------------------------
// Device scratch (allocation is banned -> __device__ globals)
// ---------------------------------------------------------------------------
__device__ float g_dec_proj[NB * ND];                  // 128 KB
__device__ float g_partials[(size_t)NB * NS * 8];      // 2 MB
__device__ __align__(16) uint4 g_We_hi4[131072];       // 2 MB    [e][k/8]
__device__ __align__(16) uint4 g_We_lo4[131072];       // 2 MB

// ---------------------------------------------------------------------------
// PTX helpers (plain sm_80/sm_90 instructions; no 'a'-suffix features)
// ---------------------------------------------------------------------------
__device__ __forceinline__ uint32_t smem_to_u32(const void* p) {
    uint32_t a;
    asm("{ .reg .u64 t; cvta.to.shared.u64 t, %1; cvt.u32.u64 %0, t; }" : "=r"(a) : "l"(p));
    return a;
}
__device__ __forceinline__ void cp_async16(uint32_t dst, const void* src) {
    asm volatile("cp.async.cg.shared.global [%0], [%1], 16;" :: "r"(dst), "l"(src) : "memory");
}
// .noinc is load-bearing: the default form is count-neutral and never trips a
// barrier pre-initialized with the thread count -> deadlock (R12 lesson).
__device__ __forceinline__ void cp_async_mbar_arrive(uint32_t mbar) {
    asm volatile("cp.async.mbarrier.arrive.noinc.shared::cta.b64 [%0];" :: "r"(mbar) : "memory");
}
#define MBARRIER_INIT(addr, cnt) \
    asm volatile("mbarrier.init.shared.b64 [%0], %1;" :: "r"((uint32_t)(addr)), "r"((uint32_t)(cnt)) : "memory")
#define MBARRIER_ARRIVE(addr) \
    asm volatile("mbarrier.arrive.shared.b64 _, [%0];" :: "r"((uint32_t)(addr)) : "memory")
#define MBARRIER_WAIT_PARITY(mbar_smem_addr, phase_parity) do { \
    uint32_t _mbar = (uint32_t)(mbar_smem_addr); \
    uint32_t _parity = (uint32_t)(phase_parity); \
    uint32_t _done; \
    asm volatile("{\n\t.reg .pred p;\n\t" \
        "mbarrier.try_wait.parity.acquire.cta.shared::cta.b64 p, [%1], %2;\n\t" \
        "selp.b32 %0, 1, 0, p;\n\t}" : "=r"(_done) : "r"(_mbar), "r"(_parity) : "memory"); \
    if (!_done) { \
        asm volatile("{\n\t.reg .pred P1;\n\t" \
            "WAIT_LOOP_%=:\n\t" \
            "mbarrier.try_wait.parity.acquire.cta.shared::cta.b64 P1, [%0], %1, 0x989680;\n\t" \
            "@P1 bra.uni WAIT_DONE_%=;\n\t" \
            "bra.uni WAIT_LOOP_%=;\n\t" \
            "WAIT_DONE_%=:\n\t}" :: "r"(_mbar), "r"(_parity) : "memory"); \
    } \
} while (0)
__device__ __forceinline__ void ldmatrix_x4(uint32_t* r, uint32_t addr) {
    asm volatile("ldmatrix.sync.aligned.m8n8.x4.shared.b16 {%0,%1,%2,%3}, [%4];"
        : "=r"(r[0]), "=r"(r[1]), "=r"(r[2]), "=r"(r[3]) : "r"(addr));
}
__device__ __forceinline__ void lds64(float2& d, uint32_t addr) {
    asm volatile("ld.shared.v2.f32 {%0,%1}, [%2];" : "=f"(d.x), "=f"(d.y) : "r"(addr));
}
// Pack two fp32 to bf16x2: lo half <- f.x, hi half <- f.y (PTX: 2nd src -> lo)
__device__ __forceinline__ uint32_t pack_hi(float2 f) {
    uint32_t r;
    asm("cvt.rn.bf16x2.f32 %0, %1, %2;" : "=r"(r) : "f"(f.y), "f"(f.x));
    return r;
}
// Residual (x - bf16(x)) pair, packed to bf16x2. Bit-identical to split8_store.
__device__ __forceinline__ uint32_t pack_lo(float2 f, uint32_t h) {
    float he = __uint_as_float(h << 16);
    float ho = __uint_as_float(h & 0xffff0000u);
    float le = f.x - he;
    float lo_ = f.y - ho;
    uint32_t r;
    asm("cvt.rn.bf16x2.f32 %0, %1, %2;" : "=r"(r) : "f"(lo_), "f"(le));
    return r;
}
__device__ __forceinline__ void mma_bf16(float* c, const uint32_t* a, const uint32_t* b) {
    asm volatile(
        "mma.sync.aligned.m16n8k16.row.col.f32.bf16.bf16.f32 "
        "{%0,%1,%2,%3}, {%4,%5,%6,%7}, {%8,%9}, {%0,%1,%2,%3};"
        : "+f"(c[0]), "+f"(c[1]), "+f"(c[2]), "+f"(c[3])
        : "r"(a[0]), "r"(a[1]), "r"(a[2]), "r"(a[3]), "r"(b[0]), "r"(b[1]));
}

// ---------------------------------------------------------------------------
// Accurate tanh (tanh.approx's ~1e-3 error would blow the budget)
// ---------------------------------------------------------------------------
__device__ __forceinline__ float tanh_acc(float x) {
    float ax = fabsf(x);
    float e  = __expf(-2.0f * ax);
    float t  = __fdividef(1.0f - e, 1.0f + e);
    return copysignf(t, x);
}

// ---------------------------------------------------------------------------
// Conversion for B only (We is 4 MB): fp32 -> exact bf16 hi/lo, row-major.
// ---------------------------------------------------------------------------
__global__ void k_convert_We(const float* __restrict__ Wa) {
    int t  = blockIdx.x * blockDim.x + threadIdx.x;   // 128K threads
    int e  = t >> 7;
    int k0 = (t & 127) * 8;
    const float* p = Wa + (size_t)e * (2 * ND) + ND + k0;   // We[e, k]
    float4 x0 = *(const float4*)p;
    float4 x1 = *(const float4*)(p + 4);
    float xs[8] = {x0.x, x0.y, x0.z, x0.w, x1.x, x1.y, x1.z, x1.w};
    unsigned short hs[8], ls[8];
#pragma unroll
    for (int i = 0; i < 8; i++) {
        __nv_bfloat16 bh = __float2bfloat16_rn(xs[i]);
        float hf = __bfloat162float(bh);
        __nv_bfloat16 bl = __float2bfloat16_rn(xs[i] - hf);
        hs[i] = __bfloat16_as_ushort(bh);
        ls[i] = __bfloat16_as_ushort(bl);
    }
    uint4 H, L;
    H.x = (uint32_t)hs[0] | ((uint32_t)hs[1] << 16);
    H.y = (uint32_t)hs[2] | ((uint32_t)hs[3] << 16);
    H.z = (uint32_t)hs[4] | ((uint32_t)hs[5] << 16);
    H.w = (uint32_t)hs[6] | ((uint32_t)hs[7] << 16);
    L.x = (uint32_t)ls[0] | ((uint32_t)ls[1] << 16);
    L.y = (uint32_t)ls[2] | ((uint32_t)ls[3] << 16);
    L.z = (uint32_t)ls[4] | ((uint32_t)ls[5] << 16);
    L.w = (uint32_t)ls[6] | ((uint32_t)ls[7] << 16);
    g_We_hi4[t] = H;
    g_We_lo4[t] = L;
}

// ---------------------------------------------------------------------------
// dec_proj[b, e] = sum_k dec[b, k] * W_a[e, k]
// grid (NB, 128), 256 threads: one warp per output element.
// ---------------------------------------------------------------------------
__global__ void k_dec_proj(const float* __restrict__ dec,
                           const float* __restrict__ Wa) {
    __shared__ float ds[ND];
    const int b = blockIdx.x;
    for (int k = threadIdx.x; k < ND; k += blockDim.x)
        ds[k] = dec[b * ND + k];
    __syncthreads();

    const int warp = threadIdx.x >> 5;
    const int lane = threadIdx.x & 31;
    const int e = blockIdx.y * 8 + warp;
    const float* w = Wa + (size_t)e * (2 * ND);
    float s = 0.0f;
#pragma unroll 8
    for (int k = lane; k < ND; k += 32)
        s = fmaf(ds[k], w[k], s);
#pragma unroll
    for (int o = 16; o; o >>= 1)
        s += __shfl_xor_sync(0xffffffffu, s, o);
    if (lane == 0)
        g_dec_proj[b * ND + e] = s;
}

// ---------------------------------------------------------------------------
// Main GEMM: mma.sync bf16 3-pass split + fused tanh/v epilogue.
// A is loaded as RAW FP32 (byte-equal to hi+lo bf16) straight from enc; the
// hi/lo A fragments are built in registers (lds.64 + cvt), eliminating the
// 512 MB k_convert_enc pass entirely. B uses pre-converted bf16 hi/lo.
// 3-stage mbarrier pipeline, free-running warps, 2 CTAs/SM.
// 256 threads = 8 warps as 4(m) x 2(n); warp tile 32(M) x 64(N).
// ---------------------------------------------------------------------------
__global__ __launch_bounds__(GT, 2)
void k_gemm_tc(const float* __restrict__ enc, const float* __restrict__ v) {
    extern __shared__ __align__(16) char smem[];
    const uint32_t smem_base = smem_to_u32(smem);

    const int tid    = threadIdx.x;
    const int wid    = tid >> 5;
    const int lane   = tid & 31;
    const int warp_m = wid & 3;         // 0..3 -> m offset *32
    const int warp_n = wid >> 2;        // 0..1 -> n offset *64
    const int nt_blk = blockIdx.x;      // 0..7
    const int mt_blk = blockIdx.y;      // 0..511
    const int m0 = mt_blk * 128;
    const int n0 = nt_blk * 128;

    // mbarriers: full[s] (256 .noinc cp.async completions), free[s] (256 arrives)
    const uint32_t mb = smem_base + MB_OFF;
    if (tid == 0) {
#pragma unroll
        for (int s = 0; s < N_STAGES; s++) {
            MBARRIER_INIT(mb + s * 8, GT);        // full[s]
            MBARRIER_INIT(mb + 24 + s * 8, GT);   // free[s]
        }
    }
    __syncthreads();

    // A: raw fp32 rows of enc (4096 B global pitch)
    const char* gA = (const char*)enc + (size_t)m0 * 4096;
    // B: pre-converted bf16 hi/lo (2048 B global pitch)
    const char* gBh = (const char*)g_We_hi4 + (size_t)n0 * 2048;
    const char* gBl = (const char*)g_We_lo4 + (size_t)n0 * 2048;

    // Per-thread copy slots.
    // A: 1024 16B-chunks per tile -> 4 per thread: row tid>>1, chunks (tid&1)*4+j
    const uint32_t rA = (uint32_t)(tid >> 1);          // 0..127
    const uint32_t cA = (uint32_t)(tid & 1) * 4;       // 0 or 4
    const size_t  soA = (size_t)rA * 4096 + cA * 16;
    uint32_t doA[4];
#pragma unroll
    for (int j = 0; j < 4; j++)
        doA[j] = swA(rA, cA + j);
    // B: 512 chunks per tile -> 2 per thread per tile
    const uint32_t rB0 = (uint32_t)(tid >> 2);         // 0..63
    const uint32_t rB1 = rB0 + 64;                     // 64..127
    const uint32_t cB  = (uint32_t)(tid & 3);
    const size_t soB0 = (size_t)rB0 * 2048 + cB * 16;
    const size_t soB1 = (size_t)rB1 * 2048 + cB * 16;
    const uint32_t doB0 = swB(rB0, cB);
    const uint32_t doB1 = swB(rB1, cB);

    // Issue this thread's 8 copies for chunk kc into stage s, bind to full[s]
    auto load_chunk = [&](int stage, int kc) {
        const uint32_t sb = smem_base + stage * STAGE_BYTES;
        const size_t koA = (size_t)kc * 128;   // fp32: 32 floats
        const size_t koB = (size_t)kc * 64;    // bf16: 32 halves
        cp_async16(sb + doA[0], gA + soA + koA);
        cp_async16(sb + doA[1], gA + soA + koA + 16);
        cp_async16(sb + doA[2], gA + soA + koA + 32);
        cp_async16(sb + doA[3], gA + soA + koA + 48);
        cp_async16(sb + A_BYTES + doB0,          gBh + soB0 + koB);
        cp_async16(sb + A_BYTES + doB1,          gBh + soB1 + koB);
        cp_async16(sb + A_BYTES + TILE_B + doB0, gBl + soB0 + koB);
        cp_async16(sb + A_BYTES + TILE_B + doB1, gBl + soB1 + koB);
        cp_async_mbar_arrive(mb + stage * 8);
    };

    float acc[2][8][4];
#pragma unroll
    for (int mt = 0; mt < 2; mt++)
#pragma unroll
        for (int nt = 0; nt < 8; nt++)
#pragma unroll
            for (int i = 0; i < 4; i++)
                acc[mt][nt][i] = 0.0f;

    // ---- Hoisted A-fragment lds offsets ----
    // m16n8k16 A frag (lane l, g=l>>2, t=l&3): float2 pairs at
    // (g,2t) (g+8,2t) (g,2t+8) (g+8,2t+8), col base ks*16.
    // All fragment rows have r&7 == g, so the XOR swizzle folds to ^g.
    const uint32_t g = (uint32_t)(lane >> 2);
    const uint32_t t = (uint32_t)(lane & 3);
    const uint32_t innerA = (t & 1) * 8;
    uint32_t coffA[2][2];   // [ks][0]=cols 2t, [1]=cols 2t+8
#pragma unroll
    for (int ks = 0; ks < 2; ks++) {
        const uint32_t cb = (uint32_t)(ks * 4) + (t >> 1);
        coffA[ks][0] = ((cb ^ g) << 4) + innerA;
        coffA[ks][1] = (((cb + 2) ^ g) << 4) + innerA;
    }
    uint32_t rbA[2][2];     // [mt][0]=row g, [1]=row g+8 (byte offsets)
#pragma unroll
    for (int mt = 0; mt < 2; mt++) {
        rbA[mt][0] = (uint32_t)(warp_m * 32 + mt * 16 + g) * 128u;
        rbA[mt][1] = rbA[mt][0] + 1024u;
    }
    // B ldmatrix offsets (kc-invariant)
    const uint32_t b_row_l = (uint32_t)(((lane >> 4) & 1) * 8 + (lane & 7));
    const uint32_t b_c_l   = (uint32_t)((lane >> 3) & 1);
    uint32_t boff[2][2][2];    // [ks][half][q], relative to stage base
#pragma unroll
    for (int ks = 0; ks < 2; ks++)
#pragma unroll
        for (int half = 0; half < 2; half++)
#pragma unroll
            for (int q = 0; q < 2; q++)
                boff[ks][half][q] =
                    swB((uint32_t)(warp_n * 64 + (half * 2 + q) * 16) + b_row_l,
                        (uint32_t)(2 * ks) + b_c_l) + A_BYTES;

    // Prologue: 2 chunks in flight
    load_chunk(0, 0);
    load_chunk(1, 1);

    for (int kc = 0; kc < NKC; kc++) {
        const int s = kc % N_STAGES;

        // Issue loads for kc+2 (WAR-guarded by free[(kc+2)%3])
        if (kc + 2 < NKC) {
            const int c2 = kc + 2;
            const int s2 = c2 % N_STAGES;
            if (c2 >= N_STAGES)
                MBARRIER_WAIT_PARITY(mb + 24 + s2 * 8, ((c2 - N_STAGES) / N_STAGES) & 1);
            load_chunk(s2, c2);
        }

        // Wait for this chunk's data
        MBARRIER_WAIT_PARITY(mb + s * 8, (kc / N_STAGES) & 1);

        const uint32_t sb = smem_base + s * STAGE_BYTES;
#pragma unroll
        for (int ks = 0; ks < 2; ks++) {
            // Build A hi/lo fragments from raw fp32 (bit-identical split)
            uint32_t aH[2][4], aL[2][4];
#pragma unroll
            for (int mt = 0; mt < 2; mt++) {
                float2 f0, f1, f2, f3;
                lds64(f0, sb + rbA[mt][0] + coffA[ks][0]);
                lds64(f1, sb + rbA[mt][1] + coffA[ks][0]);
                lds64(f2, sb + rbA[mt][0] + coffA[ks][1]);
                lds64(f3, sb + rbA[mt][1] + coffA[ks][1]);
                aH[mt][0] = pack_hi(f0);
                aH[mt][1] = pack_hi(f1);
                aH[mt][2] = pack_hi(f2);
                aH[mt][3] = pack_hi(f3);
                aL[mt][0] = pack_lo(f0, aH[mt][0]);
                aL[mt][1] = pack_lo(f1, aH[mt][1]);
                aL[mt][2] = pack_lo(f2, aH[mt][2]);
                aL[mt][3] = pack_lo(f3, aH[mt][3]);
            }
#pragma unroll
            for (int half = 0; half < 2; half++) {
                uint32_t bH[4][2], bL[4][2];
#pragma unroll
                for (int q = 0; q < 2; q++) {
                    const uint32_t off = sb + boff[ks][half][q];
                    uint32_t th[4], tl[4];
                    ldmatrix_x4(th, off);
                    ldmatrix_x4(tl, off + TILE_B);
                    bH[2 * q][0] = th[0]; bH[2 * q][1] = th[1];
                    bH[2 * q + 1][0] = th[2]; bH[2 * q + 1][1] = th[3];
                    bL[2 * q][0] = tl[0]; bL[2 * q][1] = tl[1];
                    bL[2 * q + 1][0] = tl[2]; bL[2 * q + 1][1] = tl[3];
                }
                // Last smem read of this stage: release it so producers refill
                // while the remaining MMAs run.
                if (ks == 1 && half == 1)
                    MBARRIER_ARRIVE(mb + 24 + s * 8);

                // 3 passes: Ah*Bh + Ah*Bl + Al*Bh
#pragma unroll
                for (int mt = 0; mt < 2; mt++)
#pragma unroll
                    for (int nt = 0; nt < 4; nt++)
                        mma_bf16(acc[mt][half * 4 + nt], aH[mt], bH[nt]);
#pragma unroll
                for (int mt = 0; mt < 2; mt++)
#pragma unroll
                    for (int nt = 0; nt < 4; nt++)
                        mma_bf16(acc[mt][half * 4 + nt], aH[mt], bL[nt]);
#pragma unroll
                for (int mt = 0; mt < 2; mt++)
#pragma unroll
                    for (int nt = 0; nt < 4; nt++)
                        mma_bf16(acc[mt][half * 4 + nt], aL[mt], bH[nt]);
            }
        }
    }

    // ----- Fused epilogue: tanh(acc + dec_proj)*v, reduce over n -----
    const int b = m0 >> 11;   // 2048 rows per batch
    float dv[16], vv[16];
#pragma unroll
    for (int nt = 0; nt < 8; nt++)
#pragma unroll
        for (int c = 0; c < 2; c++) {
            const int col = n0 + warp_n * 64 + nt * 8 + (lane & 3) * 2 + c;
            dv[nt * 2 + c] = g_dec_proj[b * ND + col];
            vv[nt * 2 + c] = v[col];
        }

    float* red = (float*)smem;    // 128 rows x 2 warp_n floats
    __syncthreads();              // all warps past their last smem reads

#pragma unroll
    for (int mt = 0; mt < 2; mt++)
#pragma unroll
        for (int h = 0; h < 2; h++) {
            float s = 0.0f;
#pragma unroll
            for (int nt = 0; nt < 8; nt++)
#pragma unroll
                for (int c = 0; c < 2; c++)
                    s = fmaf(tanh_acc(acc[mt][nt][h * 2 + c] + dv[nt * 2 + c]),
                             vv[nt * 2 + c], s);
            // reduce across the 4 lanes sharing this row
            s += __shfl_xor_sync(0xffffffffu, s, 1);
            s += __shfl_xor_sync(0xffffffffu, s, 2);
            if ((lane & 3) == 0) {
                const int lr = warp_m * 32 + mt * 16 + h * 8 + (lane >> 2);
                red[lr * 2 + warp_n] = s;
            }
        }
    __syncthreads();

    if (tid < 128)
        g_partials[(size_t)(m0 + tid) * 8 + nt_blk] = red[tid * 2] + red[tid * 2 + 1];
}

// ---------------------------------------------------------------------------
// Per-batch softmax over s
// ---------------------------------------------------------------------------
__global__ void k_softmax(float* __restrict__ out) {
    __shared__ float sc[NS];
    __shared__ float wred[8];
    const int b = blockIdx.x;
    const int tid = threadIdx.x;
    const int warp = tid >> 5, lane = tid & 31;

    float mx = -1e30f;
    for (int s = tid; s < NS; s += 256) {
        const float* p = &g_partials[((size_t)(b * NS + s)) * 8];
        float t = ((p[0] + p[1]) + (p[2] + p[3])) + ((p[4] + p[5]) + (p[6] + p[7]));
        sc[s] = t;
        mx = fmaxf(mx, t);
    }
#pragma unroll
    for (int o = 16; o; o >>= 1)
        mx = fmaxf(mx, __shfl_xor_sync(0xffffffffu, mx, o));
    if (lane == 0) wred[warp] = mx;
    __syncthreads();
    if (tid == 0) {
        float m = wred[0];
#pragma unroll
        for (int i = 1; i < 8; i++) m = fmaxf(m, wred[i]);
        wred[0] = m;
    }
    __syncthreads();
    const float bm = wred[0];
    __syncthreads();

    float sum = 0.0f;
    for (int s = tid; s < NS; s += 256) {
        float e = __expf(sc[s] - bm);
        sc[s] = e;
        sum += e;
    }
#pragma unroll
    for (int o = 16; o; o >>= 1)
        sum += __shfl_xor_sync(0xffffffffu, sum, o);
    if (lane == 0) wred[warp] = sum;
    __syncthreads();
    if (tid == 0) {
        float t = 0.0f;
#pragma unroll
        for (int i = 0; i < 8; i++) t += wred[i];
        wred[0] = t;
    }
    __syncthreads();
    const float inv = 1.0f / wred[0];
    for (int s = tid; s < NS; s += 256)
        out[b * NS + s] = sc[s] * inv;
}

// ---------------------------------------------------------------------------
// Launch
// ---------------------------------------------------------------------------
extern "C" void kernel_launch(void* const* d_in, const int* in_sizes, int n_in,
                              void* d_out, int out_size) {
    const float* dec = (const float*)d_in[0];
    const float* enc = (const float*)d_in[1];
    const float* Wa  = (const float*)d_in[2];
    const float* v   = (const float*)d_in[3];
    float* out = (float*)d_out;
    (void)in_sizes; (void)n_in; (void)out_size;

    cudaFuncSetAttribute(k_gemm_tc, cudaFuncAttributeMaxDynamicSharedMemorySize, SMEM_GEMM);

    k_convert_We<<<512, 256>>>(Wa);                   // B only: 4 MB
    k_dec_proj<<<dim3(NB, 128), 256>>>(dec, Wa);
    k_gemm_tc<<<dim3(NT_TILES, MT_TILES), GT, SMEM_GEMM>>>(enc, v);
    k_softmax<<<NB, 256>>>(out);
}

// round 17
// speedup vs baseline: 1.2103x; 1.2103x over previous
#include <cuda_runtime.h>
#include <cuda_bf16.h>
#include <math.h>
#include <stdint.h>

// Problem constants
#define NB 32
#define NS 2048
#define ND 1024

// GEMM tiling: CTA 128(M) x 128(N), K chunks of 32, swizzled pitch-64 smem
#define MT_TILES 512
#define NT_TILES 8
#define NKC 32
#define TILE_SM 8192
#define STAGE_BYTES (4 * TILE_SM)            // Ah, Al, Bh, Bl = 32768
#define N_STAGES 3
#define SMEM_STAGES (N_STAGES * STAGE_BYTES) // 98304
#define MB_OFF SMEM_STAGES
#define SMEM_GEMM (SMEM_STAGES + 64)         // 98368 B -> 2 CTAs/SM
#define GT 256

// Megakernel grid layout (bid order == dependency order; in-order dispatch
// guarantees every spin-gate's producers are already on the chip)
#define CONV_BLKS 512            // per quarter: 128 MB of enc
#define WE_BLKS 128
#define DEC_BLKS 256
#define GEMM_Q_BLKS 1024         // 128 m-tiles x 8 n-tiles
#define SEG_WE 512               // [512, 640)
#define SEG_DEC 640              // [640, 896)
#define SEG_GEMM0 896            // [896, 1920)
#define SEG_Q1 1920              // then (conv 512 + gemm 1024) per quarter
#define Q_STRIDE 1536
#define TOTAL_BLKS (SEG_Q1 + 3 * Q_STRIDE)   // 6528

// Swizzled byte offset of (row r, 16B-chunk c) within one tile
__device__ __forceinline__ uint32_t sw_off(uint32_t r, uint32_t c) {
    return r * 64u + ((c ^ ((r >> 1) & 3u)) * 16u);
}

// ---------------------------------------------------------------------------
// Device scratch (allocation is banned -> __device__ globals)
// ---------------------------------------------------------------------------
__device__ float g_dec_proj[NB * ND];                  // 128 KB
__device__ float g_partials[(size_t)NB * NS * 8];      // 2 MB
__device__ __align__(16) uint4 g_enc_hi4[8388608];     // 128 MB  [m][k/8]
__device__ __align__(16) uint4 g_enc_lo4[8388608];     // 128 MB
__device__ __align__(16) uint4 g_We_hi4[131072];       // 2 MB    [e][k/8]
__device__ __align__(16) uint4 g_We_lo4[131072];       // 2 MB
// Progress counters: [0..3] conv quarters, [4] We, [5] dec_proj
__device__ unsigned g_cnt[6];

// ---------------------------------------------------------------------------
// PTX helpers (plain sm_80/sm_90 instructions; no 'a'-suffix features)
// ---------------------------------------------------------------------------
__device__ __forceinline__ uint32_t smem_to_u32(const void* p) {
    uint32_t a;
    asm("{ .reg .u64 t; cvta.to.shared.u64 t, %1; cvt.u32.u64 %0, t; }" : "=r"(a) : "l"(p));
    return a;
}
__device__ __forceinline__ void cp_async16(uint32_t dst, const void* src) {
    asm volatile("cp.async.cg.shared.global [%0], [%1], 16;" :: "r"(dst), "l"(src) : "memory");
}
// .noinc is load-bearing: the default form is count-neutral and never trips a
// barrier pre-initialized with the thread count -> deadlock (R12 lesson).
__device__ __forceinline__ void cp_async_mbar_arrive(uint32_t mbar) {
    asm volatile("cp.async.mbarrier.arrive.noinc.shared::cta.b64 [%0];" :: "r"(mbar) : "memory");
}
#define MBARRIER_INIT(addr, cnt) \
    asm volatile("mbarrier.init.shared.b64 [%0], %1;" :: "r"((uint32_t)(addr)), "r"((uint32_t)(cnt)) : "memory")
#define MBARRIER_ARRIVE(addr) \
    asm volatile("mbarrier.arrive.shared.b64 _, [%0];" :: "r"((uint32_t)(addr)) : "memory")
#define MBARRIER_WAIT_PARITY(mbar_smem_addr, phase_parity) do { \
    uint32_t _mbar = (uint32_t)(mbar_smem_addr); \
    uint32_t _parity = (uint32_t)(phase_parity); \
    uint32_t _done; \
    asm volatile("{\n\t.reg .pred p;\n\t" \
        "mbarrier.try_wait.parity.acquire.cta.shared::cta.b64 p, [%1], %2;\n\t" \
        "selp.b32 %0, 1, 0, p;\n\t}" : "=r"(_done) : "r"(_mbar), "r"(_parity) : "memory"); \
    if (!_done) { \
        asm volatile("{\n\t.reg .pred P1;\n\t" \
            "WAIT_LOOP_%=:\n\t" \
            "mbarrier.try_wait.parity.acquire.cta.shared::cta.b64 P1, [%0], %1, 0x989680;\n\t" \
            "@P1 bra.uni WAIT_DONE_%=;\n\t" \
            "bra.uni WAIT_LOOP_%=;\n\t" \
            "WAIT_DONE_%=:\n\t}" :: "r"(_mbar), "r"(_parity) : "memory"); \
    } \
} while (0)
__device__ __forceinline__ void ldmatrix_x4(uint32_t* r, uint32_t addr) {
    asm volatile("ldmatrix.sync.aligned.m8n8.x4.shared.b16 {%0,%1,%2,%3}, [%4];"
        : "=r"(r[0]), "=r"(r[1]), "=r"(r[2]), "=r"(r[3]) : "r"(addr));
}
__device__ __forceinline__ void mma_bf16(float* c, const uint32_t* a, const uint32_t* b) {
    asm volatile(
        "mma.sync.aligned.m16n8k16.row.col.f32.bf16.bf16.f32 "
        "{%0,%1,%2,%3}, {%4,%5,%6,%7}, {%8,%9}, {%0,%1,%2,%3};"
        : "+f"(c[0]), "+f"(c[1]), "+f"(c[2]), "+f"(c[3])
        : "r"(a[0]), "r"(a[1]), "r"(a[2]), "r"(a[3]), "r"(b[0]), "r"(b[1]));
}
// Spin until *p == target (producers fence before their counted arrive)
__device__ __forceinline__ void spin_until(const unsigned* p, unsigned target) {
    const volatile unsigned* vp = (const volatile unsigned*)p;
    while (*vp != target)
        __nanosleep(200);
}

// ---------------------------------------------------------------------------
// Accurate tanh (tanh.approx's ~1e-3 error would blow the budget)
// ---------------------------------------------------------------------------
__device__ __forceinline__ float tanh_acc(float x) {
    float ax = fabsf(x);
    float e  = __expf(-2.0f * ax);
    float t  = __fdividef(1.0f - e, 1.0f + e);
    return copysignf(t, x);
}

// fp32 -> exact bf16 hi/lo split of 8 elements
__device__ __forceinline__ void split8_store(const float* xs, uint4* hi_dst, uint4* lo_dst) {
    unsigned short hs[8], ls[8];
#pragma unroll
    for (int i = 0; i < 8; i++) {
        __nv_bfloat16 bh = __float2bfloat16_rn(xs[i]);
        float hf = __bfloat162float(bh);
        __nv_bfloat16 bl = __float2bfloat16_rn(xs[i] - hf);
        hs[i] = __bfloat16_as_ushort(bh);
        ls[i] = __bfloat16_as_ushort(bl);
    }
    uint4 H, L;
    H.x = (uint32_t)hs[0] | ((uint32_t)hs[1] << 16);
    H.y = (uint32_t)hs[2] | ((uint32_t)hs[3] << 16);
    H.z = (uint32_t)hs[4] | ((uint32_t)hs[5] << 16);
    H.w = (uint32_t)hs[6] | ((uint32_t)hs[7] << 16);
    L.x = (uint32_t)ls[0] | ((uint32_t)ls[1] << 16);
    L.y = (uint32_t)ls[2] | ((uint32_t)ls[3] << 16);
    L.z = (uint32_t)ls[4] | ((uint32_t)ls[5] << 16);
    L.w = (uint32_t)ls[6] | ((uint32_t)ls[7] << 16);
    *hi_dst = H;
    *lo_dst = L;
}

// ---------------------------------------------------------------------------
// Reset counters (before every megakernel run; deterministic per call)
// ---------------------------------------------------------------------------
__global__ void k_reset() {
    if (threadIdx.x < 6)
        g_cnt[threadIdx.x] = 0;
}

// ---------------------------------------------------------------------------
// Megakernel: converts + dec_proj + GEMM in ONE launch, chained by bid-order
// spin gates so GEMM quarter q starts as soon as its enc quarter is ready.
// ---------------------------------------------------------------------------
__global__ __launch_bounds__(GT, 2)
void k_mega(const float* __restrict__ enc, const float* __restrict__ Wa,
            const float* __restrict__ dec, const float* __restrict__ v) {
    const int bid = blockIdx.x;
    const int tid = threadIdx.x;

    // ---------------- segment decode ----------------
    // conv quarter?
    int cq = -1, cb = 0;
    if (bid < CONV_BLKS) { cq = 0; cb = bid; }
    else if (bid >= SEG_Q1) {
        const int r = bid - SEG_Q1;
        const int rr = r % Q_STRIDE;
        if (rr < CONV_BLKS) { cq = r / Q_STRIDE + 1; cb = rr; }
    }

    if (cq >= 0) {
        // Convert 4096 uint4s (16 per thread) of enc quarter cq
        const size_t base = (size_t)cq * 2097152 + (size_t)cb * 4096 + (size_t)tid;
#pragma unroll 4
        for (int i = 0; i < 16; i++) {
            const size_t t = base + (size_t)i * 256;
            const float* p = enc + t * 8;
            float4 x0 = *(const float4*)p;
            float4 x1 = *(const float4*)(p + 4);
            float xs[8] = {x0.x, x0.y, x0.z, x0.w, x1.x, x1.y, x1.z, x1.w};
            split8_store(xs, &g_enc_hi4[t], &g_enc_lo4[t]);
        }
        __syncthreads();
        if (tid == 0) { __threadfence(); atomicAdd(&g_cnt[cq], 1u); }
        return;
    }

    if (bid < SEG_DEC) {               // We convert: bids [512, 640)
        const int wb = bid - SEG_WE;
#pragma unroll
        for (int i = 0; i < 4; i++) {
            const int t = wb * 1024 + i * 256 + tid;
            const int e = t >> 7;
            const int k0 = (t & 127) * 8;
            const float* p = Wa + (size_t)e * (2 * ND) + ND + k0;
            float4 x0 = *(const float4*)p;
            float4 x1 = *(const float4*)(p + 4);
            float xs[8] = {x0.x, x0.y, x0.z, x0.w, x1.x, x1.y, x1.z, x1.w};
            split8_store(xs, &g_We_hi4[t], &g_We_lo4[t]);
        }
        __syncthreads();
        if (tid == 0) { __threadfence(); atomicAdd(&g_cnt[4], 1u); }
        return;
    }

    if (bid < SEG_GEMM0) {             // dec_proj: bids [640, 896)
        const int db = bid - SEG_DEC;  // 0..255; 128 elems per block
        const int w = tid >> 5, lane = tid & 31;
        const int b = db >> 3;                       // 8 blocks per batch row
        const int e_base = (db & 7) * 128 + w * 16;  // 16 elems per warp
        const float* drow = dec + b * ND;
        for (int j = 0; j < 16; j++) {
            const int e = e_base + j;
            const float* wrow = Wa + (size_t)e * (2 * ND);
            float s = 0.0f;
#pragma unroll 8
            for (int k = lane; k < ND; k += 32)
                s = fmaf(drow[k], wrow[k], s);
#pragma unroll
            for (int o = 16; o; o >>= 1)
                s += __shfl_xor_sync(0xffffffffu, s, o);
            if (lane == 0)
                g_dec_proj[b * ND + e] = s;
        }
        __syncthreads();
        if (tid == 0) { __threadfence(); atomicAdd(&g_cnt[5], 1u); }
        return;
    }

    // ---------------- GEMM block ----------------
    int gq, gb;
    if (bid < SEG_Q1) { gq = 0; gb = bid - SEG_GEMM0; }
    else {
        const int r = bid - SEG_Q1;
        gq = r / Q_STRIDE + 1;
        gb = r % Q_STRIDE - CONV_BLKS;
    }
    const int nt_blk = gb & 7;
    const int mt_blk = gq * 128 + (gb >> 3);
    const int m0 = mt_blk * 128;
    const int n0 = nt_blk * 128;

    extern __shared__ __align__(16) char smem[];
    const uint32_t smem_base = smem_to_u32(smem);
    const int wid    = tid >> 5;
    const int lane   = tid & 31;
    const int warp_m = wid & 3;
    const int warp_n = wid >> 2;

    const uint32_t mb = smem_base + MB_OFF;
    if (tid == 0) {
#pragma unroll
        for (int s = 0; s < N_STAGES; s++) {
            MBARRIER_INIT(mb + s * 8, GT);        // full[s]
            MBARRIER_INIT(mb + 24 + s * 8, GT);   // free[s]
        }
        // Gate: this quarter's enc conversion + all of We must be done.
        spin_until(&g_cnt[gq], CONV_BLKS);
        spin_until(&g_cnt[4], WE_BLKS);
        __threadfence();
    }
    __syncthreads();

    const char* gAh = (const char*)g_enc_hi4 + (size_t)m0 * 2048;
    const char* gAl = (const char*)g_enc_lo4 + (size_t)m0 * 2048;
    const char* gBh = (const char*)g_We_hi4 + (size_t)n0 * 2048;
    const char* gBl = (const char*)g_We_lo4 + (size_t)n0 * 2048;

    const uint32_t rc0 = (uint32_t)(tid >> 2);
    const uint32_t rc1 = rc0 + 64;
    const uint32_t cc  = (uint32_t)(tid & 3);
    const size_t so0 = (size_t)rc0 * 2048 + cc * 16;
    const size_t so1 = (size_t)rc1 * 2048 + cc * 16;
    const uint32_t do0 = sw_off(rc0, cc);
    const uint32_t do1 = sw_off(rc1, cc);

    auto load_chunk = [&](int stage, int kc) {
        const uint32_t sb = smem_base + stage * STAGE_BYTES;
        const size_t ko = (size_t)kc * 64;
        cp_async16(sb + do0,               gAh + so0 + ko);
        cp_async16(sb + do1,               gAh + so1 + ko);
        cp_async16(sb + TILE_SM + do0,     gAl + so0 + ko);
        cp_async16(sb + TILE_SM + do1,     gAl + so1 + ko);
        cp_async16(sb + 2 * TILE_SM + do0, gBh + so0 + ko);
        cp_async16(sb + 2 * TILE_SM + do1, gBh + so1 + ko);
        cp_async16(sb + 3 * TILE_SM + do0, gBl + so0 + ko);
        cp_async16(sb + 3 * TILE_SM + do1, gBl + so1 + ko);
        cp_async_mbar_arrive(mb + stage * 8);
    };

    float acc[2][8][4];
#pragma unroll
    for (int mt = 0; mt < 2; mt++)
#pragma unroll
        for (int nt = 0; nt < 8; nt++)
#pragma unroll
            for (int i = 0; i < 4; i++)
                acc[mt][nt][i] = 0.0f;

    const uint32_t a_row_l = (uint32_t)((lane & 7) + ((lane >> 3) & 1) * 8);
    const uint32_t a_c_l   = (uint32_t)(lane >> 4);
    const uint32_t b_row_l = (uint32_t)(((lane >> 4) & 1) * 8 + (lane & 7));
    const uint32_t b_c_l   = (uint32_t)((lane >> 3) & 1);

    uint32_t aoff[2][2];
    uint32_t boff[2][2][2];
#pragma unroll
    for (int ks = 0; ks < 2; ks++) {
#pragma unroll
        for (int mt = 0; mt < 2; mt++)
            aoff[ks][mt] = sw_off((uint32_t)(warp_m * 32 + mt * 16) + a_row_l,
                                  (uint32_t)(2 * ks) + a_c_l);
#pragma unroll
        for (int half = 0; half < 2; half++)
#pragma unroll
            for (int q = 0; q < 2; q++)
                boff[ks][half][q] =
                    sw_off((uint32_t)(warp_n * 64 + (half * 2 + q) * 16) + b_row_l,
                           (uint32_t)(2 * ks) + b_c_l) + 2u * TILE_SM;
    }

    load_chunk(0, 0);
    load_chunk(1, 1);

    for (int kc = 0; kc < NKC; kc++) {
        const int s = kc % N_STAGES;

        if (kc + 2 < NKC) {
            const int c2 = kc + 2;
            const int s2 = c2 % N_STAGES;
            if (c2 >= N_STAGES)
                MBARRIER_WAIT_PARITY(mb + 24 + s2 * 8, ((c2 - N_STAGES) / N_STAGES) & 1);
            load_chunk(s2, c2);
        }

        MBARRIER_WAIT_PARITY(mb + s * 8, (kc / N_STAGES) & 1);

        const uint32_t sb = smem_base + s * STAGE_BYTES;
#pragma unroll
        for (int ks = 0; ks < 2; ks++) {
            uint32_t aH[2][4], aL[2][4];
#pragma unroll
            for (int mt = 0; mt < 2; mt++) {
                ldmatrix_x4(aH[mt], sb + aoff[ks][mt]);
                ldmatrix_x4(aL[mt], sb + TILE_SM + aoff[ks][mt]);
            }
#pragma unroll
            for (int half = 0; half < 2; half++) {
                uint32_t bH[4][2], bL[4][2];
#pragma unroll
                for (int q = 0; q < 2; q++) {
                    const uint32_t off = sb + boff[ks][half][q];
                    uint32_t th[4], tl[4];
                    ldmatrix_x4(th, off);
                    ldmatrix_x4(tl, off + TILE_SM);
                    bH[2 * q][0] = th[0]; bH[2 * q][1] = th[1];
                    bH[2 * q + 1][0] = th[2]; bH[2 * q + 1][1] = th[3];
                    bL[2 * q][0] = tl[0]; bL[2 * q][1] = tl[1];
                    bL[2 * q + 1][0] = tl[2]; bL[2 * q + 1][1] = tl[3];
                }
                if (ks == 1 && half == 1)
                    MBARRIER_ARRIVE(mb + 24 + s * 8);

                // 3 passes: Ah*Bh + Ah*Bl + Al*Bh
#pragma unroll
                for (int mt = 0; mt < 2; mt++)
#pragma unroll
                    for (int nt = 0; nt < 4; nt++)
                        mma_bf16(acc[mt][half * 4 + nt], aH[mt], bH[nt]);
#pragma unroll
                for (int mt = 0; mt < 2; mt++)
#pragma unroll
                    for (int nt = 0; nt < 4; nt++)
                        mma_bf16(acc[mt][half * 4 + nt], aH[mt], bL[nt]);
#pragma unroll
                for (int mt = 0; mt < 2; mt++)
#pragma unroll
                    for (int nt = 0; nt < 4; nt++)
                        mma_bf16(acc[mt][half * 4 + nt], aL[mt], bH[nt]);
            }
        }
    }

    // ----- Fused epilogue: tanh(acc + dec_proj)*v, reduce over n -----
    if (tid == 0) {
        spin_until(&g_cnt[5], DEC_BLKS);   // dec_proj ready (long done by now)
        __threadfence();
    }
    const int b = m0 >> 11;
    float* red = (float*)smem;
    __syncthreads();    // also orders the dec gate for all threads

    float dv[16], vv[16];
#pragma unroll
    for (int nt = 0; nt < 8; nt++)
#pragma unroll
        for (int c = 0; c < 2; c++) {
            const int col = n0 + warp_n * 64 + nt * 8 + (lane & 3) * 2 + c;
            dv[nt * 2 + c] = g_dec_proj[b * ND + col];
            vv[nt * 2 + c] = v[col];
        }

#pragma unroll
    for (int mt = 0; mt < 2; mt++)
#pragma unroll
        for (int h = 0; h < 2; h++) {
            float s = 0.0f;
#pragma unroll
            for (int nt = 0; nt < 8; nt++)
#pragma unroll
                for (int c = 0; c < 2; c++)
                    s = fmaf(tanh_acc(acc[mt][nt][h * 2 + c] + dv[nt * 2 + c]),
                             vv[nt * 2 + c], s);
            s += __shfl_xor_sync(0xffffffffu, s, 1);
            s += __shfl_xor_sync(0xffffffffu, s, 2);
            if ((lane & 3) == 0) {
                const int lr = warp_m * 32 + mt * 16 + h * 8 + (lane >> 2);
                red[lr * 2 + warp_n] = s;
            }
        }
    __syncthreads();

    if (tid < 128)
        g_partials[(size_t)(m0 + tid) * 8 + nt_blk] = red[tid * 2] + red[tid * 2 + 1];
}

// ---------------------------------------------------------------------------
// Per-batch softmax over s
// ---------------------------------------------------------------------------
__global__ void k_softmax(float* __restrict__ out) {
    __shared__ float sc[NS];
    __shared__ float wred[8];
    const int b = blockIdx.x;
    const int tid = threadIdx.x;
    const int warp = tid >> 5, lane = tid & 31;

    float mx = -1e30f;
    for (int s = tid; s < NS; s += 256) {
        const float* p = &g_partials[((size_t)(b * NS + s)) * 8];
        float t = ((p[0] + p[1]) + (p[2] + p[3])) + ((p[4] + p[5]) + (p[6] + p[7]));
        sc[s] = t;
        mx = fmaxf(mx, t);
    }
#pragma unroll
    for (int o = 16; o; o >>= 1)
        mx = fmaxf(mx, __shfl_xor_sync(0xffffffffu, mx, o));
    if (lane == 0) wred[warp] = mx;
    __syncthreads();
    if (tid == 0) {
        float m = wred[0];
#pragma unroll
        for (int i = 1; i < 8; i++) m = fmaxf(m, wred[i]);
        wred[0] = m;
    }
    __syncthreads();
    const float bm = wred[0];
    __syncthreads();

    float sum = 0.0f;
    for (int s = tid; s < NS; s += 256) {
        float e = __expf(sc[s] - bm);
        sc[s] = e;
        sum += e;
    }
#pragma unroll
    for (int o = 16; o; o >>= 1)
        sum += __shfl_xor_sync(0xffffffffu, sum, o);
    if (lane == 0) wred[warp] = sum;
    __syncthreads();
    if (tid == 0) {
        float t = 0.0f;
#pragma unroll
        for (int i = 0; i < 8; i++) t += wred[i];
        wred[0] = t;
    }
    __syncthreads();
    const float inv = 1.0f / wred[0];
    for (int s = tid; s < NS; s += 256)
        out[b * NS + s] = sc[s] * inv;
}

// ---------------------------------------------------------------------------
// Launch: reset counters, one megakernel (converts + dec_proj + GEMM chained
// by in-order block dispatch + spin gates), then softmax. No streams, no
// events, no allocations.
// ---------------------------------------------------------------------------
extern "C" void kernel_launch(void* const* d_in, const int* in_sizes, int n_in,
                              void* d_out, int out_size) {
    const float* dec = (const float*)d_in[0];
    const float* enc = (const float*)d_in[1];
    const float* Wa  = (const float*)d_in[2];
    const float* v   = (const float*)d_in[3];
    float* out = (float*)d_out;
    (void)in_sizes; (void)n_in; (void)out_size;

    cudaFuncSetAttribute(k_mega, cudaFuncAttributeMaxDynamicSharedMemorySize,
                         SMEM_GEMM);

    k_reset<<<1, 32>>>();
    k_mega<<<TOTAL_BLKS, GT, SMEM_GEMM>>>(enc, Wa, dec, v);
    k_softmax<<<NB, 256>>>(out);
}